// round 10
// baseline (speedup 1.0000x reference)
#include <cuda_runtime.h>
#include <cuda_fp16.h>
#include <cstdint>

// ============================================================================
// Problem constants
// ============================================================================
#define NN   8192
#define DIMN 256
#define TMB  64            // rows per CTA
#define KT   64            // j (K) per tile
#define NT   (NN / KT)     // 128 tiles

// ============================================================================
// Device scratch
// ============================================================================
__device__ float  g_h1[NN];
__device__ float  g_h2[NN];
__device__ __half g_hf[(size_t)NN * DIMN];   // h in fp16, same [N][D] layout

// ============================================================================
// SMEM layout (padded strides -> conflict-free ldmatrix phases)
// ============================================================================
#define W_STRIDE 72        // halves per row (144 B)
#define H_STRIDE 264       // halves per row (528 B)
#define WBUF (TMB * W_STRIDE * 2)    // 9216 B
#define HBUF (KT  * H_STRIDE * 2)    // 33792 B
#define SOFF_W   0
#define SOFF_H   (2 * WBUF)              // 18432
#define SOFF_H1  (SOFF_H + 2 * HBUF)     // 86016
#define SOFF_Z   (SOFF_H1 + 256)         // 86272
#define SMEMSZ   (SOFF_Z + 256)          // 86528

// ============================================================================
// Helpers
// ============================================================================
__device__ __forceinline__ uint32_t smem_u32(const void* p) {
    uint32_t a;
    asm("{ .reg .u64 t; cvta.to.shared.u64 t, %1; cvt.u32.u64 %0, t; }" : "=r"(a) : "l"(p));
    return a;
}

// weight = exp(lrelu(s) - 4); shift cancels in softmax, keeps fp16 in range
__device__ __forceinline__ float wcalc(float s, int mask) {
    float lr = fmaxf(s, 0.f) + 0.01f * fminf(s, 0.f);
    float e;
    asm("ex2.approx.ftz.f32 %0, %1;" : "=f"(e) : "f"(fmaf(lr, 1.44269504f, -5.7707801634f)));
    return mask > 0 ? e : 0.f;
}

#define MMA16816(c0, c1, c2, c3, a0, a1, a2, a3, b0, b1)                       \
    asm volatile(                                                              \
        "mma.sync.aligned.m16n8k16.row.col.f32.f16.f16.f32 "                   \
        "{%0,%1,%2,%3},{%4,%5,%6,%7},{%8,%9},{%0,%1,%2,%3};"                   \
        : "+f"(c0), "+f"(c1), "+f"(c2), "+f"(c3)                               \
        : "r"(a0), "r"(a1), "r"(a2), "r"(a3), "r"(b0), "r"(b1))

#define LDSM_X4(r0, r1, r2, r3, addr)                                          \
    asm volatile("ldmatrix.sync.aligned.m8n8.x4.shared.b16 {%0,%1,%2,%3},[%4];"\
        : "=r"(r0), "=r"(r1), "=r"(r2), "=r"(r3) : "r"(addr))

#define LDSM_X4T(r0, r1, r2, r3, addr)                                         \
    asm volatile("ldmatrix.sync.aligned.m8n8.x4.trans.shared.b16 {%0,%1,%2,%3},[%4];" \
        : "=r"(r0), "=r"(r1), "=r"(r2), "=r"(r3) : "r"(addr))

#define CP_ASYNC16(dst, src)                                                   \
    asm volatile("cp.async.cg.shared.global [%0], [%1], 16;"                   \
        :: "r"(dst), "l"(__cvta_generic_to_global(src)) : "memory")
#define CP_COMMIT()  asm volatile("cp.async.commit_group;" ::: "memory")
#define CP_WAIT0()   asm volatile("cp.async.wait_group 0;" ::: "memory")

// ============================================================================
// Fused prep kernel: h1/h2 GEMV + fp16 conversion of h (single pass over h)
// ============================================================================
__global__ void gat_prep(const float* __restrict__ h, const float* __restrict__ a) {
    int row  = blockIdx.x * 8 + (threadIdx.x >> 5);
    int lane = threadIdx.x & 31;
    const float4* hr = (const float4*)(h + (size_t)row * DIMN);
    const float4* a1 = (const float4*)a;
    const float4* a2 = (const float4*)(a + DIMN);

    float4 hv0 = hr[lane];
    float4 hv1 = hr[lane + 32];
    float4 av10 = __ldg(&a1[lane]);      float4 av11 = __ldg(&a1[lane + 32]);
    float4 av20 = __ldg(&a2[lane]);      float4 av21 = __ldg(&a2[lane + 32]);

    float s1 = hv0.x * av10.x + hv0.y * av10.y + hv0.z * av10.z + hv0.w * av10.w
             + hv1.x * av11.x + hv1.y * av11.y + hv1.z * av11.z + hv1.w * av11.w;
    float s2 = hv0.x * av20.x + hv0.y * av20.y + hv0.z * av20.z + hv0.w * av20.w
             + hv1.x * av21.x + hv1.y * av21.y + hv1.z * av21.z + hv1.w * av21.w;

    union { __half2 p[2]; uint2 u; } U0, U1;
    U0.p[0] = __floats2half2_rn(hv0.x, hv0.y);  U0.p[1] = __floats2half2_rn(hv0.z, hv0.w);
    U1.p[0] = __floats2half2_rn(hv1.x, hv1.y);  U1.p[1] = __floats2half2_rn(hv1.z, hv1.w);
    uint2* dst = (uint2*)(g_hf + (size_t)row * DIMN);
    dst[lane]      = U0.u;
    dst[lane + 32] = U1.u;

#pragma unroll
    for (int o = 16; o; o >>= 1) {
        s1 += __shfl_xor_sync(0xFFFFFFFFu, s1, o);
        s2 += __shfl_xor_sync(0xFFFFFFFFu, s2, o);
    }
    if (lane == 0) { g_h1[row] = s1; g_h2[row] = s2; }
}

// ============================================================================
// W tile compute: 8 elements per thread (row = tid>>3, cols (tid&7)*8..+7)
// ============================================================================
__device__ __forceinline__ void compute_w8(
    char* wbuf, int row, int cg,
    int4 a0, int4 a1, float4 f0, float4 f1,
    float h1v, float& zacc)
{
    float wv[8];
    wv[0] = wcalc(h1v + f0.x, a0.x); wv[1] = wcalc(h1v + f0.y, a0.y);
    wv[2] = wcalc(h1v + f0.z, a0.z); wv[3] = wcalc(h1v + f0.w, a0.w);
    wv[4] = wcalc(h1v + f1.x, a1.x); wv[5] = wcalc(h1v + f1.y, a1.y);
    wv[6] = wcalc(h1v + f1.z, a1.z); wv[7] = wcalc(h1v + f1.w, a1.w);

    union { __half2 p[4]; uint4 u; } P;
#pragma unroll
    for (int i = 0; i < 4; i++)
        P.p[i] = __floats2half2_rn(wv[2 * i], wv[2 * i + 1]);
    // accumulate ROUNDED weights so numerator/denominator stay consistent
#pragma unroll
    for (int i = 0; i < 4; i++) {
        float2 z = __half22float2(P.p[i]);
        zacc += z.x + z.y;
    }
    *(uint4*)(wbuf + row * (W_STRIDE * 2) + cg * 16) = P.u;
}

// ============================================================================
// Main fused kernel: 128 CTAs x 512 threads (16 warps); each CTA: 64 rows, full K
// Warp tiling 2x8: 32 rows x 32 cols per warp.
// K-step phase rotation: warp w starts at ks=(w>>2)&3 so the 4 warps on each
// SMSP are desynchronized -> LDSM (crossbar) and MMA (tensor) phases interleave
// instead of convoying.
// ============================================================================
__global__ void __launch_bounds__(512, 1)
gat_main(const int* __restrict__ adj, float* __restrict__ out) {
    extern __shared__ char smem[];
    const int tid  = threadIdx.x;
    const int lane = tid & 31;
    const int wid  = tid >> 5;
    const int m0   = blockIdx.x * TMB;

    uint32_t sb = smem_u32(smem);
    float* h1s = (float*)(smem + SOFF_H1);
    float* zsh = (float*)(smem + SOFF_Z);

    if (tid < TMB) h1s[tid] = g_h1[m0 + tid];
    __syncthreads();

    // warp tile: 32 rows x 32 cols
    const int wm = wid & 1, wn = wid >> 1;
    const int mbase = wm * 32;
    const int nbase = wn * 32;
    const int kphase = (wid >> 2) & 3;   // per-SMSP stagger (SMSP = wid & 3)

    float acc[32];
#pragma unroll
    for (int i = 0; i < 32; i++) acc[i] = 0.f;
    float zacc = 0.f;

    const int row = tid >> 3, cg = tid & 7;   // W-compute mapping: 64 rows x 8 col-groups
    const float h1v = h1s[row];

    // ldmatrix lane address components
    const int l8 = lane & 7, g01 = (lane >> 3) & 1, g2 = lane >> 4;
    const uint32_t aoff0 = (uint32_t)(mbase +      g01 * 8 + l8) * (W_STRIDE * 2) + (uint32_t)(g2 * 8) * 2;
    const uint32_t aoff1 = (uint32_t)(mbase + 16 + g01 * 8 + l8) * (W_STRIDE * 2) + (uint32_t)(g2 * 8) * 2;
    const uint32_t boff  = (uint32_t)(g01 * 8 + l8) * (H_STRIDE * 2) + (uint32_t)(nbase + g2 * 8) * 2;

    int4   pa0, pa1;
    float4 pf0, pf1;

    // ---- prologue: tile 0 into buffer 0 ----
    {
#pragma unroll
        for (int it = 0; it < 4; it++) {
            int q = it * 512 + tid;
            uint32_t dst = sb + SOFF_H + (uint32_t)(q >> 5) * (H_STRIDE * 2) + (q & 31) * 16;
            CP_ASYNC16(dst, g_hf + (size_t)(q >> 5) * DIMN + (q & 31) * 8);
        }
        CP_COMMIT();
        const int4* ap = (const int4*)(adj + (size_t)(m0 + row) * NN + cg * 8);
        pa0 = __ldcs(ap); pa1 = __ldcs(ap + 1);
        const float4* fp = (const float4*)(g_h2 + cg * 8);
        pf0 = __ldg(fp); pf1 = __ldg(fp + 1);
        compute_w8(smem + SOFF_W, row, cg, pa0, pa1, pf0, pf1, h1v, zacc);
        CP_WAIT0();
        __syncthreads();
    }

    // ---- main loop: one sync per tile; next-tile prep interleaved ----
    for (int t = 0; t < NT; t++) {
        const int buf = t & 1;
        const uint32_t wb = sb + SOFF_W + (uint32_t)buf * WBUF;
        const uint32_t hb = sb + SOFF_H + (uint32_t)buf * HBUF;
        const bool more = (t + 1 < NT);

        if (more) {
            const int j1 = (t + 1) * KT;
#pragma unroll
            for (int it = 0; it < 4; it++) {
                int q = it * 512 + tid;
                uint32_t dst = sb + SOFF_H + (uint32_t)(buf ^ 1) * HBUF +
                               (uint32_t)(q >> 5) * (H_STRIDE * 2) + (q & 31) * 16;
                CP_ASYNC16(dst, g_hf + (size_t)(j1 + (q >> 5)) * DIMN + (q & 31) * 8);
            }
            CP_COMMIT();
            const int4* ap = (const int4*)(adj + (size_t)(m0 + row) * NN + j1 + cg * 8);
            pa0 = __ldcs(ap); pa1 = __ldcs(ap + 1);
            const float4* fp = (const float4*)(g_h2 + j1 + cg * 8);
            pf0 = __ldg(fp); pf1 = __ldg(fp + 1);
        }

        // MMA over tile t, K-steps rotated per warp: kq = (ks + kphase) & 3.
        // All fragments are resident after the barrier, so order is free.
#pragma unroll
        for (int ks = 0; ks < 4; ks++) {
            const uint32_t kq  = (uint32_t)((ks + kphase) & 3);
            const uint32_t ka  = kq * 32;                          // A k-offset bytes
            const uint32_t kb  = kq * (uint32_t)(16 * H_STRIDE * 2); // B k-offset bytes
            uint32_t a0, a1, a2, a3, a4, a5, a6, a7;
            LDSM_X4(a0, a1, a2, a3, wb + aoff0 + ka);
            LDSM_X4(a4, a5, a6, a7, wb + aoff1 + ka);
            uint32_t b0, b1, b2, b3, b4, b5, b6, b7;
            LDSM_X4T(b0, b1, b2, b3, hb + kb + boff);
            LDSM_X4T(b4, b5, b6, b7, hb + kb + boff + 32);
            MMA16816(acc[0],  acc[1],  acc[2],  acc[3],  a0, a1, a2, a3, b0, b1);
            MMA16816(acc[4],  acc[5],  acc[6],  acc[7],  a0, a1, a2, a3, b2, b3);
            MMA16816(acc[8],  acc[9],  acc[10], acc[11], a0, a1, a2, a3, b4, b5);
            MMA16816(acc[12], acc[13], acc[14], acc[15], a0, a1, a2, a3, b6, b7);
            MMA16816(acc[16], acc[17], acc[18], acc[19], a4, a5, a6, a7, b0, b1);
            MMA16816(acc[20], acc[21], acc[22], acc[23], a4, a5, a6, a7, b2, b3);
            MMA16816(acc[24], acc[25], acc[26], acc[27], a4, a5, a6, a7, b4, b5);
            MMA16816(acc[28], acc[29], acc[30], acc[31], a4, a5, a6, a7, b6, b7);

            if (ks == 1 && more)
                compute_w8(smem + SOFF_W + (buf ^ 1) * WBUF, row, cg,
                           pa0, pa1, pf0, pf1, h1v, zacc);
        }

        if (more) CP_WAIT0();
        __syncthreads();
    }

    // ---- epilogue: reduce Z (8 threads per row), scale, store ----
    zacc += __shfl_xor_sync(0xFFFFFFFFu, zacc, 1);
    zacc += __shfl_xor_sync(0xFFFFFFFFu, zacc, 2);
    zacc += __shfl_xor_sync(0xFFFFFFFFu, zacc, 4);
    if ((lane & 7) == 0) zsh[row] = zacc;
    __syncthreads();

#pragma unroll
    for (int ms = 0; ms < 2; ms++) {
        const int   r    = mbase + ms * 16 + (lane >> 2);
        const float inv0 = 1.f / zsh[r];
        const float inv1 = 1.f / zsh[r + 8];
        const size_t gr  = (size_t)(m0 + r) * DIMN;
#pragma unroll
        for (int nc = 0; nc < 2; nc++) {
#pragma unroll
            for (int half = 0; half < 2; half++) {
                const int col = nbase + nc * 16 + half * 8 + (lane & 3) * 2;
                const int i0  = ms * 16 + nc * 8 + half * 4;
                float2 v0 = { acc[i0 + 0] * inv0, acc[i0 + 1] * inv0 };
                float2 v1 = { acc[i0 + 2] * inv1, acc[i0 + 3] * inv1 };
                *(float2*)(out + gr + col)            = v0;
                *(float2*)(out + gr + 8 * DIMN + col) = v1;
            }
        }
    }
}

// ============================================================================
// Launch
// ============================================================================
extern "C" void kernel_launch(void* const* d_in, const int* in_sizes, int n_in,
                              void* d_out, int out_size) {
    const float* h   = (const float*)d_in[0];   // [8192, 256] fp32
    const int*   adj = (const int*)d_in[1];     // [8192, 8192] int32
    const float* a   = (const float*)d_in[2];   // [512, 1] fp32
    float* out = (float*)d_out;                 // [8192, 256] fp32

    cudaFuncSetAttribute(gat_main, cudaFuncAttributeMaxDynamicSharedMemorySize, SMEMSZ);

    gat_prep<<<NN / 8, 256>>>(h, a);
    gat_main<<<NN / TMB, 512, SMEMSZ>>>(adj, out);   // 128 CTAs x 16 warps
}

// round 12
// speedup vs baseline: 1.2246x; 1.2246x over previous
#include <cuda_runtime.h>
#include <cuda_fp16.h>
#include <cstdint>

// ============================================================================
// Problem constants
// ============================================================================
#define NN   8192
#define DIMN 256
#define TMB  64            // rows per CTA
#define KT   64            // j (K) per tile
#define NT   (NN / KT)     // 128 tiles

// ============================================================================
// Device scratch
// ============================================================================
__device__ float  g_h1[NN];
__device__ float  g_h2[NN];
__device__ __half g_hf[(size_t)NN * DIMN];   // h in fp16, same [N][D] layout

// ============================================================================
// SMEM layout
// ============================================================================
#define W_STRIDE 72        // halves per row (144 B)
#define H_STRIDE 264       // halves per row (528 B)
#define WBUF (TMB * W_STRIDE * 2)    // 9216 B
#define HBUF (KT  * H_STRIDE * 2)    // 33792 B
#define ABUF (TMB * KT * 4)          // 16384 B (adj tile, row-major 64x64 int32)
#define SOFF_W   0                        // 2 x 9216
#define SOFF_H   (2 * WBUF)               // 18432: 2 x 33792
#define SOFF_ADJ (SOFF_H + 2 * HBUF)      // 86016: 2 x 16384
#define SOFF_H2  (SOFF_ADJ + 2 * ABUF)    // 118784: 32768 (all of g_h2)
#define SOFF_H1  (SOFF_H2 + NN * 4)       // 151552: 256
#define SOFF_Z   (SOFF_H1 + 256)          // 151808: 256
#define SMEMSZ   (SOFF_Z + 256)           // 152064

// ============================================================================
// Helpers
// ============================================================================
__device__ __forceinline__ uint32_t smem_u32(const void* p) {
    uint32_t a;
    asm("{ .reg .u64 t; cvta.to.shared.u64 t, %1; cvt.u32.u64 %0, t; }" : "=r"(a) : "l"(p));
    return a;
}

// weight = exp(lrelu(s) - 4); shift cancels in softmax, keeps fp16 in range
__device__ __forceinline__ float wcalc(float s, int mask) {
    float lr = fmaxf(s, 0.f) + 0.01f * fminf(s, 0.f);
    float e;
    asm("ex2.approx.ftz.f32 %0, %1;" : "=f"(e) : "f"(fmaf(lr, 1.44269504f, -5.7707801634f)));
    return mask > 0 ? e : 0.f;
}

#define MMA16816(c0, c1, c2, c3, a0, a1, a2, a3, b0, b1)                       \
    asm volatile(                                                              \
        "mma.sync.aligned.m16n8k16.row.col.f32.f16.f16.f32 "                   \
        "{%0,%1,%2,%3},{%4,%5,%6,%7},{%8,%9},{%0,%1,%2,%3};"                   \
        : "+f"(c0), "+f"(c1), "+f"(c2), "+f"(c3)                               \
        : "r"(a0), "r"(a1), "r"(a2), "r"(a3), "r"(b0), "r"(b1))

#define LDSM_X4(r0, r1, r2, r3, addr)                                          \
    asm volatile("ldmatrix.sync.aligned.m8n8.x4.shared.b16 {%0,%1,%2,%3},[%4];"\
        : "=r"(r0), "=r"(r1), "=r"(r2), "=r"(r3) : "r"(addr))

#define LDSM_X4T(r0, r1, r2, r3, addr)                                         \
    asm volatile("ldmatrix.sync.aligned.m8n8.x4.trans.shared.b16 {%0,%1,%2,%3},[%4];" \
        : "=r"(r0), "=r"(r1), "=r"(r2), "=r"(r3) : "r"(addr))

#define CP_ASYNC16(dst, src)                                                   \
    asm volatile("cp.async.cg.shared.global [%0], [%1], 16;"                   \
        :: "r"(dst), "l"(__cvta_generic_to_global(src)) : "memory")
#define CP_COMMIT()  asm volatile("cp.async.commit_group;" ::: "memory")
#define CP_WAIT0()   asm volatile("cp.async.wait_group 0;" ::: "memory")

// ============================================================================
// Fused prep kernel: h1/h2 GEMV + fp16 conversion of h (single pass over h)
// ============================================================================
__global__ void gat_prep(const float* __restrict__ h, const float* __restrict__ a) {
    int row  = blockIdx.x * 8 + (threadIdx.x >> 5);
    int lane = threadIdx.x & 31;
    const float4* hr = (const float4*)(h + (size_t)row * DIMN);
    const float4* a1 = (const float4*)a;
    const float4* a2 = (const float4*)(a + DIMN);

    float4 hv0 = hr[lane];
    float4 hv1 = hr[lane + 32];
    float4 av10 = __ldg(&a1[lane]);      float4 av11 = __ldg(&a1[lane + 32]);
    float4 av20 = __ldg(&a2[lane]);      float4 av21 = __ldg(&a2[lane + 32]);

    float s1 = hv0.x * av10.x + hv0.y * av10.y + hv0.z * av10.z + hv0.w * av10.w
             + hv1.x * av11.x + hv1.y * av11.y + hv1.z * av11.z + hv1.w * av11.w;
    float s2 = hv0.x * av20.x + hv0.y * av20.y + hv0.z * av20.z + hv0.w * av20.w
             + hv1.x * av21.x + hv1.y * av21.y + hv1.z * av21.z + hv1.w * av21.w;

    union { __half2 p[2]; uint2 u; } U0, U1;
    U0.p[0] = __floats2half2_rn(hv0.x, hv0.y);  U0.p[1] = __floats2half2_rn(hv0.z, hv0.w);
    U1.p[0] = __floats2half2_rn(hv1.x, hv1.y);  U1.p[1] = __floats2half2_rn(hv1.z, hv1.w);
    uint2* dst = (uint2*)(g_hf + (size_t)row * DIMN);
    dst[lane]      = U0.u;
    dst[lane + 32] = U1.u;

#pragma unroll
    for (int o = 16; o; o >>= 1) {
        s1 += __shfl_xor_sync(0xFFFFFFFFu, s1, o);
        s2 += __shfl_xor_sync(0xFFFFFFFFu, s2, o);
    }
    if (lane == 0) { g_h1[row] = s1; g_h2[row] = s2; }
}

// ============================================================================
// W tile compute: 8 elements per thread (row = tid>>3, cols (tid&7)*8..+7)
// adj and h2 both come from SMEM (latency pre-hidden by cp.async / prologue).
// ============================================================================
__device__ __forceinline__ void compute_w8(
    char* wbuf, int row, int cg,
    int4 a0, int4 a1, float4 f0, float4 f1,
    float h1v, float& zacc)
{
    float wv[8];
    wv[0] = wcalc(h1v + f0.x, a0.x); wv[1] = wcalc(h1v + f0.y, a0.y);
    wv[2] = wcalc(h1v + f0.z, a0.z); wv[3] = wcalc(h1v + f0.w, a0.w);
    wv[4] = wcalc(h1v + f1.x, a1.x); wv[5] = wcalc(h1v + f1.y, a1.y);
    wv[6] = wcalc(h1v + f1.z, a1.z); wv[7] = wcalc(h1v + f1.w, a1.w);

    union { __half2 p[4]; uint4 u; } P;
#pragma unroll
    for (int i = 0; i < 4; i++)
        P.p[i] = __floats2half2_rn(wv[2 * i], wv[2 * i + 1]);
    // accumulate ROUNDED weights so numerator/denominator stay consistent
#pragma unroll
    for (int i = 0; i < 4; i++) {
        float2 z = __half22float2(P.p[i]);
        zacc += z.x + z.y;
    }
    *(uint4*)(wbuf + row * (W_STRIDE * 2) + cg * 16) = P.u;
}

// ============================================================================
// Main fused kernel: 128 CTAs x 512 threads (16 warps); each CTA: 64 rows, full K
// Warp tiling 2x8: 32 rows x 32 cols per warp.
// adj streamed by cp.async with prefetch distance 2 (SMEM ring of 2 tiles):
//   group committed at tile t = { h(t+1), adj(t+2) }; wait_group 0 at tile end.
//   => adj(t+1) is resident a FULL tile before compute_w8(t+1) reads it.
// adj SMEM fill mapping (FIXED from R11): tile is 64 rows x 256 B;
//   thread covers 32 B at (row = tid>>3, byte col = (tid&7)*32),
//   512 threads x 32 B = 16384 B ✓; matches compute_w8's (row, cg) mapping.
// ============================================================================
__global__ void __launch_bounds__(512, 1)
gat_main(const int* __restrict__ adj, float* __restrict__ out) {
    extern __shared__ char smem[];
    const int tid  = threadIdx.x;
    const int lane = tid & 31;
    const int wid  = tid >> 5;
    const int m0   = blockIdx.x * TMB;

    uint32_t sb = smem_u32(smem);
    float* h1s = (float*)(smem + SOFF_H1);
    float* zsh = (float*)(smem + SOFF_Z);
    float* h2s = (float*)(smem + SOFF_H2);

    // warp tile: 32 rows x 32 cols
    const int wm = wid & 1, wn = wid >> 1;
    const int mbase = wm * 32;
    const int nbase = wn * 32;

    float acc[32];
#pragma unroll
    for (int i = 0; i < 32; i++) acc[i] = 0.f;
    float zacc = 0.f;

    const int row = tid >> 3, cg = tid & 7;   // W-compute mapping: 64 rows x 8 col-groups

    // ldmatrix lane address components
    const int l8 = lane & 7, g01 = (lane >> 3) & 1, g2 = lane >> 4;
    const uint32_t aoff0 = (uint32_t)(mbase +      g01 * 8 + l8) * (W_STRIDE * 2) + (uint32_t)(g2 * 8) * 2;
    const uint32_t aoff1 = (uint32_t)(mbase + 16 + g01 * 8 + l8) * (W_STRIDE * 2) + (uint32_t)(g2 * 8) * 2;
    const uint32_t boff  = (uint32_t)(g01 * 8 + l8) * (H_STRIDE * 2) + (uint32_t)(nbase + g2 * 8) * 2;

    // adj SMEM tile addressing: (row, cg) -> row*256 + cg*32 bytes, 2 chunks/thread
    const uint32_t a_sdst = (uint32_t)(row * 256 + cg * 32);
    const size_t   a_gsrc = (size_t)(m0 + row) * NN + (size_t)cg * 8;   // + j per tile

    // ---- prologue ----
    {
        // stage all of g_h2 into SMEM (2048 float4 = 4 per thread)
#pragma unroll
        for (int it = 0; it < 4; it++) {
            int q = it * 512 + tid;
            ((float4*)h2s)[q] = ((const float4*)g_h2)[q];
        }
        if (tid < TMB) h1s[tid] = g_h1[m0 + tid];

        // cp.async: h tile 0, adj tiles 0 and 1
#pragma unroll
        for (int it = 0; it < 4; it++) {
            int q = it * 512 + tid;
            uint32_t dst = sb + SOFF_H + (uint32_t)(q >> 5) * (H_STRIDE * 2) + (q & 31) * 16;
            CP_ASYNC16(dst, g_hf + (size_t)(q >> 5) * DIMN + (q & 31) * 8);
        }
        {
            const int* asrc0 = adj + a_gsrc;           // tile 0
            CP_ASYNC16(sb + SOFF_ADJ + a_sdst,      asrc0);
            CP_ASYNC16(sb + SOFF_ADJ + a_sdst + 16, asrc0 + 4);
            const int* asrc1 = adj + a_gsrc + KT;      // tile 1
            CP_ASYNC16(sb + SOFF_ADJ + ABUF + a_sdst,      asrc1);
            CP_ASYNC16(sb + SOFF_ADJ + ABUF + a_sdst + 16, asrc1 + 4);
        }
        CP_COMMIT();
        CP_WAIT0();
        __syncthreads();

        // compute W(0) from SMEM adj(0) + SMEM h2
        const float h1v0 = h1s[row];
        int4 pa0 = *(const int4*)(smem + SOFF_ADJ + a_sdst);
        int4 pa1 = *(const int4*)(smem + SOFF_ADJ + a_sdst + 16);
        float4 pf0 = *(const float4*)(h2s + cg * 8);
        float4 pf1 = *(const float4*)(h2s + cg * 8 + 4);
        compute_w8(smem + SOFF_W, row, cg, pa0, pa1, pf0, pf1, h1v0, zacc);
        __syncthreads();
    }

    const float h1v = h1s[row];

    // ---- main loop: one sync per tile; next-tile prep interleaved ----
    for (int t = 0; t < NT; t++) {
        const int buf = t & 1;
        const uint32_t wb = sb + SOFF_W + (uint32_t)buf * WBUF;
        const uint32_t hb = sb + SOFF_H + (uint32_t)buf * HBUF;
        const bool more = (t + 1 < NT);

        int4   pa0, pa1;
        float4 pf0, pf1;
        if (more) {
            const int j1 = (t + 1) * KT;
            // cp.async h(t+1)
#pragma unroll
            for (int it = 0; it < 4; it++) {
                int q = it * 512 + tid;
                uint32_t dst = sb + SOFF_H + (uint32_t)(buf ^ 1) * HBUF +
                               (uint32_t)(q >> 5) * (H_STRIDE * 2) + (q & 31) * 16;
                CP_ASYNC16(dst, g_hf + (size_t)(j1 + (q >> 5)) * DIMN + (q & 31) * 8);
            }
            // cp.async adj(t+2) into ring slot (t&1)  [adj(t) there, already consumed]
            if (t + 2 < NT) {
                const int* asrc = adj + a_gsrc + (size_t)(t + 2) * KT;
                uint32_t adst = sb + SOFF_ADJ + (uint32_t)buf * ABUF + a_sdst;
                CP_ASYNC16(adst,      asrc);
                CP_ASYNC16(adst + 16, asrc + 4);
            }
            CP_COMMIT();
            // adj(t+1) from SMEM ring slot ((t+1)&1) — landed a full tile ago
            const char* aslot = smem + SOFF_ADJ + (size_t)(buf ^ 1) * ABUF;
            pa0 = *(const int4*)(aslot + a_sdst);
            pa1 = *(const int4*)(aslot + a_sdst + 16);
            pf0 = *(const float4*)(h2s + j1 + cg * 8);
            pf1 = *(const float4*)(h2s + j1 + cg * 8 + 4);
        }

        // MMA over tile t (ptxas schedules the unrolled body)
#pragma unroll
        for (int ks = 0; ks < 4; ks++) {
            uint32_t a0, a1, a2, a3, a4, a5, a6, a7;
            LDSM_X4(a0, a1, a2, a3, wb + aoff0 + (uint32_t)(ks * 16) * 2);
            LDSM_X4(a4, a5, a6, a7, wb + aoff1 + (uint32_t)(ks * 16) * 2);
            uint32_t b0, b1, b2, b3, b4, b5, b6, b7;
            LDSM_X4T(b0, b1, b2, b3,
                     hb + (uint32_t)(ks * 16) * (H_STRIDE * 2) + boff);
            LDSM_X4T(b4, b5, b6, b7,
                     hb + (uint32_t)(ks * 16) * (H_STRIDE * 2) + boff + 32);
            MMA16816(acc[0],  acc[1],  acc[2],  acc[3],  a0, a1, a2, a3, b0, b1);
            MMA16816(acc[4],  acc[5],  acc[6],  acc[7],  a0, a1, a2, a3, b2, b3);
            MMA16816(acc[8],  acc[9],  acc[10], acc[11], a0, a1, a2, a3, b4, b5);
            MMA16816(acc[12], acc[13], acc[14], acc[15], a0, a1, a2, a3, b6, b7);
            MMA16816(acc[16], acc[17], acc[18], acc[19], a4, a5, a6, a7, b0, b1);
            MMA16816(acc[20], acc[21], acc[22], acc[23], a4, a5, a6, a7, b2, b3);
            MMA16816(acc[24], acc[25], acc[26], acc[27], a4, a5, a6, a7, b4, b5);
            MMA16816(acc[28], acc[29], acc[30], acc[31], a4, a5, a6, a7, b6, b7);

            if (ks == 1 && more)
                compute_w8(smem + SOFF_W + (buf ^ 1) * WBUF, row, cg,
                           pa0, pa1, pf0, pf1, h1v, zacc);
        }

        if (more) CP_WAIT0();
        __syncthreads();
    }

    // ---- epilogue: reduce Z (8 threads per row), scale, store ----
    zacc += __shfl_xor_sync(0xFFFFFFFFu, zacc, 1);
    zacc += __shfl_xor_sync(0xFFFFFFFFu, zacc, 2);
    zacc += __shfl_xor_sync(0xFFFFFFFFu, zacc, 4);
    if ((lane & 7) == 0) zsh[row] = zacc;
    __syncthreads();

#pragma unroll
    for (int ms = 0; ms < 2; ms++) {
        const int   r    = mbase + ms * 16 + (lane >> 2);
        const float inv0 = 1.f / zsh[r];
        const float inv1 = 1.f / zsh[r + 8];
        const size_t gr  = (size_t)(m0 + r) * DIMN;
#pragma unroll
        for (int nc = 0; nc < 2; nc++) {
#pragma unroll
            for (int half = 0; half < 2; half++) {
                const int col = nbase + nc * 16 + half * 8 + (lane & 3) * 2;
                const int i0  = ms * 16 + nc * 8 + half * 4;
                float2 v0 = { acc[i0 + 0] * inv0, acc[i0 + 1] * inv0 };
                float2 v1 = { acc[i0 + 2] * inv1, acc[i0 + 3] * inv1 };
                *(float2*)(out + gr + col)            = v0;
                *(float2*)(out + gr + 8 * DIMN + col) = v1;
            }
        }
    }
}

// ============================================================================
// Launch
// ============================================================================
extern "C" void kernel_launch(void* const* d_in, const int* in_sizes, int n_in,
                              void* d_out, int out_size) {
    const float* h   = (const float*)d_in[0];   // [8192, 256] fp32
    const int*   adj = (const int*)d_in[1];     // [8192, 8192] int32
    const float* a   = (const float*)d_in[2];   // [512, 1] fp32
    float* out = (float*)d_out;                 // [8192, 256] fp32

    cudaFuncSetAttribute(gat_main, cudaFuncAttributeMaxDynamicSharedMemorySize, SMEMSZ);

    gat_prep<<<NN / 8, 256>>>(h, a);
    gat_main<<<NN / TMB, 512, SMEMSZ>>>(adj, out);   // 128 CTAs x 16 warps
}